// round 12
// baseline (speedup 1.0000x reference)
#include <cuda_runtime.h>

typedef unsigned long long ull;

#define T_STEPS 1024
#define BATCH   64
#define NCTA    128
#define NTHR    768

// xg0 = x @ Wih0 is hoisted out of the recurrence (no sequential dependency):
// precomputed per-CTA into g_xg0[cta][t][16 cols][64 b] (512MB), read back 4KB/step.
// Recurrence per step then does only:
//   L0: gates0 += Whh0^T h0_{t-1}   (512 rows x 16 cols)
//   L1: gates1 += Wih1^T h0_{t-1} + Whh1^T h1_{t-2}  (512+256 rows x 8 cols)
// Warp split (24 warps), boundary-aligned, each v row read by exactly one warp:
//   warps 0-15 : L0, h0 rows [32w, 32w+32), 16 cols, ring-4 LDG prefetch
//   warps 16-19: L1 part A, h0 rows [128wi, +128), 8 cols, ring-8
//   warps 20-23: L1 part B, h1 rows [64wi, +64),   8 cols, ring-8
// Lane: pg=(lane>>1) -> pairs 2pg,2pg+1; cl=lane&1 -> col half.
// Reduction: ONE write wave (16 L0 slots + 8 L1 slots) + ONE sum wave. 2 syncs.

__device__ float g_xT[T_STEPS * 256 * BATCH];     // 64MB: x transposed [t][k][b]
__device__ float g_xg0[134217728];                // 512MB: [cta][t][col16][b64]
__device__ float g_h0[2][512 * BATCH];
__device__ float g_h1[2][256 * BATCH];
__device__ unsigned g_count = 0;
__device__ volatile unsigned g_phase = 0;

__device__ __forceinline__ ull ffma2(ull a, ull b, ull c) {
    ull d;
    asm("fma.rn.f32x2 %0, %1, %2, %3;" : "=l"(d) : "l"(a), "l"(b), "l"(c));
    return d;
}
__device__ __forceinline__ ull addf2(ull a, ull b) {
    ull d;
    asm("add.rn.f32x2 %0, %1, %2;" : "=l"(d) : "l"(a), "l"(b));
    return d;
}
__device__ __forceinline__ ull dup32(float w) {
    unsigned u = __float_as_uint(w);
    return ((ull)u << 32) | (ull)u;
}
__device__ __forceinline__ float sigmf(float x) {
    return 1.0f / (1.0f + __expf(-x));
}

// Sense-reversing grid barrier. Safe: ~203KB smem -> 1 CTA/SM, 128 CTAs <= 148 SMs,
// all co-resident in wave 1. Count self-resets -> consistent across graph replays.
__device__ __forceinline__ void grid_barrier() {
    __syncthreads();
    if (threadIdx.x == 0) {
        __threadfence();
        unsigned ph = g_phase;
        if (atomicAdd(&g_count, 1u) == (unsigned)(gridDim.x - 1)) {
            atomicExch(&g_count, 0u);
            __threadfence();
            g_phase = ph + 1u;
        } else {
            while (g_phase == ph) { __nanosleep(32); }
            __threadfence();
        }
    }
    __syncthreads();
}

// NR-row GEMM slice: 8 cols x 2 pair-ulls, ring-4 global prefetch.
// vsrc: ulonglong2 base (already + pg); row stride 16 ulonglong2 (256B).
template<int NR>
__device__ __forceinline__ void gemm_c8(const ulonglong2* __restrict__ vsrc,
                                        const ull* __restrict__ wp,
                                        ull* __restrict__ a) {
    ulonglong2 rg[4];
#pragma unroll
    for (int i = 0; i < 4; i++) rg[i] = vsrc[i * 16];
#pragma unroll 4
    for (int r = 0; r < NR - 4; r++) {
        ulonglong2 v = rg[r & 3];
        rg[r & 3] = vsrc[(r + 4) * 16];
        const ull* w = wp + r * 16;
        ulonglong2 wA = *reinterpret_cast<const ulonglong2*>(w);
        ulonglong2 wB = *reinterpret_cast<const ulonglong2*>(w + 2);
        ulonglong2 wC = *reinterpret_cast<const ulonglong2*>(w + 4);
        ulonglong2 wD = *reinterpret_cast<const ulonglong2*>(w + 6);
        a[0]  = ffma2(wA.x, v.x, a[0]);   a[1]  = ffma2(wA.x, v.y, a[1]);
        a[2]  = ffma2(wA.y, v.x, a[2]);   a[3]  = ffma2(wA.y, v.y, a[3]);
        a[4]  = ffma2(wB.x, v.x, a[4]);   a[5]  = ffma2(wB.x, v.y, a[5]);
        a[6]  = ffma2(wB.y, v.x, a[6]);   a[7]  = ffma2(wB.y, v.y, a[7]);
        a[8]  = ffma2(wC.x, v.x, a[8]);   a[9]  = ffma2(wC.x, v.y, a[9]);
        a[10] = ffma2(wC.y, v.x, a[10]);  a[11] = ffma2(wC.y, v.y, a[11]);
        a[12] = ffma2(wD.x, v.x, a[12]);  a[13] = ffma2(wD.x, v.y, a[13]);
        a[14] = ffma2(wD.y, v.x, a[14]);  a[15] = ffma2(wD.y, v.y, a[15]);
    }
#pragma unroll
    for (int r = NR - 4; r < NR; r++) {
        ulonglong2 v = rg[r & 3];
        const ull* w = wp + r * 16;
        ulonglong2 wA = *reinterpret_cast<const ulonglong2*>(w);
        ulonglong2 wB = *reinterpret_cast<const ulonglong2*>(w + 2);
        ulonglong2 wC = *reinterpret_cast<const ulonglong2*>(w + 4);
        ulonglong2 wD = *reinterpret_cast<const ulonglong2*>(w + 6);
        a[0]  = ffma2(wA.x, v.x, a[0]);   a[1]  = ffma2(wA.x, v.y, a[1]);
        a[2]  = ffma2(wA.y, v.x, a[2]);   a[3]  = ffma2(wA.y, v.y, a[3]);
        a[4]  = ffma2(wB.x, v.x, a[4]);   a[5]  = ffma2(wB.x, v.y, a[5]);
        a[6]  = ffma2(wB.y, v.x, a[6]);   a[7]  = ffma2(wB.y, v.y, a[7]);
        a[8]  = ffma2(wC.x, v.x, a[8]);   a[9]  = ffma2(wC.x, v.y, a[9]);
        a[10] = ffma2(wC.y, v.x, a[10]);  a[11] = ffma2(wC.y, v.y, a[11]);
        a[12] = ffma2(wD.x, v.x, a[12]);  a[13] = ffma2(wD.x, v.y, a[13]);
        a[14] = ffma2(wD.y, v.x, a[14]);  a[15] = ffma2(wD.y, v.y, a[15]);
    }
}

// NR-row GEMM slice: 4 cols x 2 pair-ulls, ring-8 global prefetch.
template<int NR>
__device__ __forceinline__ void gemm_c4(const ulonglong2* __restrict__ vsrc,
                                        const ull* __restrict__ wp,
                                        ull* __restrict__ a) {
    ulonglong2 rg[8];
#pragma unroll
    for (int i = 0; i < 8; i++) rg[i] = vsrc[i * 16];
#pragma unroll 8
    for (int r = 0; r < NR - 8; r++) {
        ulonglong2 v = rg[r & 7];
        rg[r & 7] = vsrc[(r + 8) * 16];
        const ull* w = wp + r * 8;
        ulonglong2 wA = *reinterpret_cast<const ulonglong2*>(w);
        ulonglong2 wB = *reinterpret_cast<const ulonglong2*>(w + 2);
        a[0] = ffma2(wA.x, v.x, a[0]);  a[1] = ffma2(wA.x, v.y, a[1]);
        a[2] = ffma2(wA.y, v.x, a[2]);  a[3] = ffma2(wA.y, v.y, a[3]);
        a[4] = ffma2(wB.x, v.x, a[4]);  a[5] = ffma2(wB.x, v.y, a[5]);
        a[6] = ffma2(wB.y, v.x, a[6]);  a[7] = ffma2(wB.y, v.y, a[7]);
    }
#pragma unroll
    for (int r = NR - 8; r < NR; r++) {
        ulonglong2 v = rg[r & 7];
        const ull* w = wp + r * 8;
        ulonglong2 wA = *reinterpret_cast<const ulonglong2*>(w);
        ulonglong2 wB = *reinterpret_cast<const ulonglong2*>(w + 2);
        a[0] = ffma2(wA.x, v.x, a[0]);  a[1] = ffma2(wA.x, v.y, a[1]);
        a[2] = ffma2(wA.y, v.x, a[2]);  a[3] = ffma2(wA.y, v.y, a[3]);
        a[4] = ffma2(wB.x, v.x, a[4]);  a[5] = ffma2(wB.x, v.y, a[5]);
        a[6] = ffma2(wB.y, v.x, a[6]);  a[7] = ffma2(wB.y, v.y, a[7]);
    }
}

__global__ void __launch_bounds__(NTHR, 1)
lstm2_kernel(const float* __restrict__ x,
             const float* __restrict__ Wih0, const float* __restrict__ bih0,
             const float* __restrict__ Whh0, const float* __restrict__ bhh0,
             const float* __restrict__ Wih1, const float* __restrict__ bih1,
             const float* __restrict__ Whh1, const float* __restrict__ bhh1,
             float* __restrict__ out)
{
    extern __shared__ char smraw[];
    ull*   w0d    = reinterpret_cast<ull*>(smraw);            // [512][16] Whh0, lane-dup
    ull*   w1d    = w0d + 512 * 16;                           // [768][8]  Wih1+Whh1
    float* bcol   = reinterpret_cast<float*>(w1d + 768 * 8);  // [24] pad 32
    float* gates0 = bcol + 32;                                // [16][64]
    float* gates1 = gates0 + 16 * BATCH;                      // [8][64]
    ull*   red0   = reinterpret_cast<ull*>(gates1 + 8 * BATCH); // [16][16][32]
    ull*   red1   = red0 + 16 * 16 * 32;                      // [8][8][32]
    ull*   wih    = red0;                                     // precompute alias: [256][16]

    const int tid  = threadIdx.x;
    const int cta  = blockIdx.x;
    const int wrp  = tid >> 5;
    const int lane = tid & 31;
    const int pg   = lane >> 1;          // pair group 0..15 (pairs 2pg,2pg+1)
    const int cl   = lane & 1;           // col half
    const int cc   = tid >> 5;           // reduce mapping (tid<512)
    const int pr   = tid & 31;

    // ---- one-time: transpose x (B,T,K) -> g_xT (T,K,B) ----
    {
        const size_t total = (size_t)BATCH * T_STEPS * 64;    // float4 groups
        for (size_t idx = (size_t)cta * NTHR + tid; idx < total; idx += (size_t)NCTA * NTHR) {
            int b  = (int)(idx & 63);
            size_t r = idx >> 6;
            int kg = (int)(r & 63);
            int t  = (int)(r >> 6);
            float4 v4 = *reinterpret_cast<const float4*>(
                x + ((size_t)b * T_STEPS + t) * 256 + kg * 4);
            float* dst = g_xT + ((size_t)t * 256 + kg * 4) * BATCH + b;
            dst[0 * BATCH] = v4.x;
            dst[1 * BATCH] = v4.y;
            dst[2 * BATCH] = v4.z;
            dst[3 * BATCH] = v4.w;
        }
    }

    // ---- one-time: stage weights into smem (lane-duplicated for f32x2) ----
    // w0d col cc = g*4 + u -> Whh0 global col j = g*512 + cta*4 + u
    for (int idx = tid; idx < 512 * 16; idx += NTHR) {
        int k = idx >> 4, c = idx & 15;
        int g = c >> 2, u = c & 3;
        int j = g * 512 + cta * 4 + u;
        w0d[idx] = dup32(Whh0[(size_t)k * 2048 + j]);
    }
    // w1d col c = g*2 + u1 -> global j = g*256 + cta*2 + u1
    for (int idx = tid; idx < 768 * 8; idx += NTHR) {
        int k = idx >> 3, c = idx & 7;
        int g = c >> 1, u1 = c & 1;
        int j = g * 256 + cta * 2 + u1;
        float w = (k < 512) ? Wih1[(size_t)k * 1024 + j]
                            : Whh1[(size_t)(k - 512) * 1024 + j];
        w1d[idx] = dup32(w);
    }
    // wih (aliased on red0): [256][16] from Wih0, for the precompute phase
    for (int idx = tid; idx < 256 * 16; idx += NTHR) {
        int k = idx >> 4, c = idx & 15;
        int g = c >> 2, u = c & 3;
        int j = g * 512 + cta * 4 + u;
        wih[idx] = dup32(Wih0[(size_t)k * 2048 + j]);
    }
    if (tid < 16) {
        int g = tid >> 2, u = tid & 3;
        int j = g * 512 + cta * 4 + u;
        bcol[tid] = bih0[j] + bhh0[j];
    } else if (tid < 24) {
        int c = tid - 16, g = c >> 1, u1 = c & 1;
        int j = g * 256 + cta * 2 + u1;
        bcol[tid] = bih1[j] + bhh1[j];
    }

    __syncthreads();
    grid_barrier();     // g_xT complete (read by all CTAs below)

    // ---- phase 1: precompute xg0[t] = Wih0^T x_t for own 16 cols, all t ----
    for (int t = wrp; t < T_STEPS; t += 24) {
        ull a[16];
#pragma unroll
        for (int j = 0; j < 16; j++) a[j] = 0ull;
        gemm_c8<256>(reinterpret_cast<const ulonglong2*>(
                         g_xT + (size_t)t * 16384) + pg,
                     wih + cl * 8, a);
        float* dst = g_xg0 + ((size_t)cta * T_STEPS + t) * 1024 + (cl * 8) * 64 + 4 * pg;
#pragma unroll
        for (int j = 0; j < 8; j++)
            *reinterpret_cast<ulonglong2*>(dst + j * 64) =
                make_ulonglong2(a[2 * j], a[2 * j + 1]);
    }
    __syncthreads();    // wih (red0) now free for reduction use

    float cst = 0.0f;   // c0 for tid<256 (unit tid>>6, batch tid&63); c1 for [256,384)

    // ---- phase 2: recurrence. iteration t = layer0 step t + layer1 step t-1 ----
    for (int t = 0; t <= T_STEPS; t++) {
        const bool hasL0 = (t < T_STEPS);
        const bool hasL1 = (t >= 1);

        // early xg0 fetch (used ~5K cyc later in the reduce) — DRAM latency covered
        ull xg = 0ull;
        if (hasL0 && tid < 512)
            xg = *reinterpret_cast<const ull*>(
                g_xg0 + ((size_t)cta * T_STEPS + t) * 1024 + cc * 64 + 2 * pr);

        if (wrp < 16) {
            // ---- L0: h0 rows [32wrp, 32wrp+32), 16 cols ----
            ull a0[16];
#pragma unroll
            for (int j = 0; j < 16; j++) a0[j] = 0ull;
            if (hasL0 && t >= 1)
                gemm_c8<32>(reinterpret_cast<const ulonglong2*>(
                                g_h0[(t - 1) & 1] + wrp * 2048) + pg,
                            w0d + wrp * 32 * 16 + cl * 8, a0);
#pragma unroll
            for (int j = 0; j < 8; j++)
                *reinterpret_cast<ulonglong2*>(
                    red0 + ((cl * 8 + j) * 16 + wrp) * 32 + 2 * pg) =
                    make_ulonglong2(a0[2 * j], a0[2 * j + 1]);
        } else if (wrp < 20) {
            // ---- L1 part A: h0 rows [128wi, +128), 8 cols ----
            const int wi = wrp - 16;
            ull a1[8];
#pragma unroll
            for (int j = 0; j < 8; j++) a1[j] = 0ull;
            if (hasL1)
                gemm_c4<128>(reinterpret_cast<const ulonglong2*>(
                                 g_h0[(t - 1) & 1] + wi * 128 * 64) + pg,
                             w1d + wi * 128 * 8 + cl * 4, a1);
#pragma unroll
            for (int j = 0; j < 4; j++)
                *reinterpret_cast<ulonglong2*>(
                    red1 + ((cl * 4 + j) * 8 + wi) * 32 + 2 * pg) =
                    make_ulonglong2(a1[2 * j], a1[2 * j + 1]);
        } else {
            // ---- L1 part B: h1 rows [64wi, +64), 8 cols ----
            const int wi = wrp - 20;
            ull a1[8];
#pragma unroll
            for (int j = 0; j < 8; j++) a1[j] = 0ull;
            if (hasL1 && t >= 2)
                gemm_c4<64>(reinterpret_cast<const ulonglong2*>(
                                g_h1[t & 1] + wi * 64 * 64) + pg,
                            w1d + (512 + wi * 64) * 8 + cl * 4, a1);
#pragma unroll
            for (int j = 0; j < 4; j++)
                *reinterpret_cast<ulonglong2*>(
                    red1 + ((cl * 4 + j) * 8 + (wrp - 16)) * 32 + 2 * pg) =
                    make_ulonglong2(a1[2 * j], a1[2 * j + 1]);
        }
        __syncthreads();

        // ---- final reduce: gates = bias (+xg0) + sum of slots ----
        if (tid < 512) {
            const ull* r = red0 + (cc * 16) * 32 + pr;
            ull s = addf2(xg, dup32(bcol[cc]));
#pragma unroll
            for (int w = 0; w < 16; w++) s = addf2(s, r[w * 32]);
            *reinterpret_cast<ull*>(&gates0[cc * 64 + 2 * pr]) = s;
        } else {
            const int c1 = (tid - 512) >> 5, p1 = tid & 31;
            const ull* r = red1 + (c1 * 8) * 32 + p1;
            ull s = dup32(bcol[16 + c1]);
#pragma unroll
            for (int w = 0; w < 8; w++) s = addf2(s, r[w * 32]);
            *reinterpret_cast<ull*>(&gates1[c1 * 64 + 2 * p1]) = s;
        }
        __syncthreads();

        // ---- activations (disjoint warps) ----
        if (hasL0 && tid < 256) {
            int u = tid >> 6, b = tid & 63;
            float gi = gates0[(0 * 4 + u) * 64 + b];
            float gf = gates0[(1 * 4 + u) * 64 + b];
            float gg = gates0[(2 * 4 + u) * 64 + b];
            float go = gates0[(3 * 4 + u) * 64 + b];
            cst = sigmf(gf) * cst + sigmf(gi) * tanhf(gg);
            g_h0[t & 1][(cta * 4 + u) * 64 + b] = sigmf(go) * tanhf(cst);
        }
        if (hasL1 && tid >= 256 && tid < 384) {
            int u1 = (tid >> 6) & 1, b = tid & 63;
            float gi = gates1[(0 * 2 + u1) * 64 + b];
            float gf = gates1[(1 * 2 + u1) * 64 + b];
            float gg = gates1[(2 * 2 + u1) * 64 + b];
            float go = gates1[(3 * 2 + u1) * 64 + b];
            cst = sigmf(gf) * cst + sigmf(gi) * tanhf(gg);
            float h = sigmf(go) * tanhf(cst);
            int s = t - 1;
            g_h1[s & 1][(cta * 2 + u1) * 64 + b] = h;
            out[((size_t)b * T_STEPS + s) * 256 + cta * 2 + u1] = h;
        }

        if (t < T_STEPS) grid_barrier();
    }
}

// smem: w0d 65536 + w1d 49152 + bcol 128 + gates 6144 + red0 65536 + red1 16384 = 202880
#define SMEM_BYTES (65536 + 49152 + 128 + 4096 + 2048 + 65536 + 16384)

extern "C" void kernel_launch(void* const* d_in, const int* in_sizes, int n_in,
                              void* d_out, int out_size) {
    (void)in_sizes; (void)n_in; (void)out_size;
    cudaFuncSetAttribute(lstm2_kernel,
                         cudaFuncAttributeMaxDynamicSharedMemorySize, SMEM_BYTES);
    lstm2_kernel<<<NCTA, NTHR, SMEM_BYTES>>>(
        (const float*)d_in[0],
        (const float*)d_in[1], (const float*)d_in[2],
        (const float*)d_in[3], (const float*)d_in[4],
        (const float*)d_in[5], (const float*)d_in[6],
        (const float*)d_in[7], (const float*)d_in[8],
        (float*)d_out);
}

// round 13
// speedup vs baseline: 1.0172x; 1.0172x over previous
#include <cuda_runtime.h>

typedef unsigned long long ull;

#define T_STEPS 1024
#define BATCH   64
#define NCTA    128
#define NTHR    768

// xg0 = x @ Wih0 hoisted out of the recurrence (no sequential dependency):
// phase 1 precomputes g_xg0[cta][t][16 cols][64 b] (512MB), read back 4KB/step.
// Recurrence per step:
//   L0: gates0 = xg0 + bias + Whh0^T h0_{t-1}        (512 rows x 16 cols)
//   L1: gates1 = bias + Wih1^T h0_{t-1} + Whh1^T h1_{t-2}  (512+256 rows x 8 cols)
// BALANCED warp split (24 warps, no duplicate v reads, no h0/h1 straddle):
//   warps 0-15 : L0 h0 rows [22w,+22)           + L1 h0 rows [32w,+32)    = 608 ffma2/lane
//   warps 16-23: L0 h0 rows [352+20w',+20)      + L1 h1 rows [32w',+32)   = 576 ffma2/lane
// Lane: pg=(lane>>1) -> pairs 2pg,2pg+1; cl=lane&1 -> col half.
// Accums: a0[16] + a1[8] = 24 ull. 2-wave reduction into 12 slots (2 syncs).

__device__ float g_xT[T_STEPS * 256 * BATCH];     // 64MB: x transposed [t][k][b]
__device__ float g_xg0[134217728];                // 512MB: [cta][t][col16][b64]
__device__ float g_h0[2][512 * BATCH];
__device__ float g_h1[2][256 * BATCH];
__device__ unsigned g_count = 0;
__device__ volatile unsigned g_phase = 0;

__device__ __forceinline__ ull ffma2(ull a, ull b, ull c) {
    ull d;
    asm("fma.rn.f32x2 %0, %1, %2, %3;" : "=l"(d) : "l"(a), "l"(b), "l"(c));
    return d;
}
__device__ __forceinline__ ull addf2(ull a, ull b) {
    ull d;
    asm("add.rn.f32x2 %0, %1, %2;" : "=l"(d) : "l"(a), "l"(b));
    return d;
}
__device__ __forceinline__ ull dup32(float w) {
    unsigned u = __float_as_uint(w);
    return ((ull)u << 32) | (ull)u;
}
__device__ __forceinline__ float sigmf(float x) {
    return 1.0f / (1.0f + __expf(-x));
}

// Sense-reversing grid barrier. Safe: ~195KB smem -> 1 CTA/SM, 128 CTAs <= 148 SMs,
// all co-resident in wave 1. Count self-resets -> consistent across graph replays.
__device__ __forceinline__ void grid_barrier() {
    __syncthreads();
    if (threadIdx.x == 0) {
        __threadfence();
        unsigned ph = g_phase;
        if (atomicAdd(&g_count, 1u) == (unsigned)(gridDim.x - 1)) {
            atomicExch(&g_count, 0u);
            __threadfence();
            g_phase = ph + 1u;
        } else {
            while (g_phase == ph) { __nanosleep(32); }
            __threadfence();
        }
    }
    __syncthreads();
}

// NR-row GEMM slice: 8 cols x 2 pair-ulls, ring-4 global prefetch.
// vsrc: ulonglong2 base (already + pg); row stride 16 ulonglong2 (256B).
template<int NR>
__device__ __forceinline__ void gemm_c8(const ulonglong2* __restrict__ vsrc,
                                        const ull* __restrict__ wp,
                                        ull* __restrict__ a) {
    ulonglong2 rg[4];
#pragma unroll
    for (int i = 0; i < 4; i++) rg[i] = vsrc[i * 16];
#pragma unroll 4
    for (int r = 0; r < NR - 4; r++) {
        ulonglong2 v = rg[r & 3];
        rg[r & 3] = vsrc[(r + 4) * 16];
        const ull* w = wp + r * 16;
        ulonglong2 wA = *reinterpret_cast<const ulonglong2*>(w);
        ulonglong2 wB = *reinterpret_cast<const ulonglong2*>(w + 2);
        ulonglong2 wC = *reinterpret_cast<const ulonglong2*>(w + 4);
        ulonglong2 wD = *reinterpret_cast<const ulonglong2*>(w + 6);
        a[0]  = ffma2(wA.x, v.x, a[0]);   a[1]  = ffma2(wA.x, v.y, a[1]);
        a[2]  = ffma2(wA.y, v.x, a[2]);   a[3]  = ffma2(wA.y, v.y, a[3]);
        a[4]  = ffma2(wB.x, v.x, a[4]);   a[5]  = ffma2(wB.x, v.y, a[5]);
        a[6]  = ffma2(wB.y, v.x, a[6]);   a[7]  = ffma2(wB.y, v.y, a[7]);
        a[8]  = ffma2(wC.x, v.x, a[8]);   a[9]  = ffma2(wC.x, v.y, a[9]);
        a[10] = ffma2(wC.y, v.x, a[10]);  a[11] = ffma2(wC.y, v.y, a[11]);
        a[12] = ffma2(wD.x, v.x, a[12]);  a[13] = ffma2(wD.x, v.y, a[13]);
        a[14] = ffma2(wD.y, v.x, a[14]);  a[15] = ffma2(wD.y, v.y, a[15]);
    }
#pragma unroll
    for (int r = NR - 4; r < NR; r++) {
        ulonglong2 v = rg[r & 3];
        const ull* w = wp + r * 16;
        ulonglong2 wA = *reinterpret_cast<const ulonglong2*>(w);
        ulonglong2 wB = *reinterpret_cast<const ulonglong2*>(w + 2);
        ulonglong2 wC = *reinterpret_cast<const ulonglong2*>(w + 4);
        ulonglong2 wD = *reinterpret_cast<const ulonglong2*>(w + 6);
        a[0]  = ffma2(wA.x, v.x, a[0]);   a[1]  = ffma2(wA.x, v.y, a[1]);
        a[2]  = ffma2(wA.y, v.x, a[2]);   a[3]  = ffma2(wA.y, v.y, a[3]);
        a[4]  = ffma2(wB.x, v.x, a[4]);   a[5]  = ffma2(wB.x, v.y, a[5]);
        a[6]  = ffma2(wB.y, v.x, a[6]);   a[7]  = ffma2(wB.y, v.y, a[7]);
        a[8]  = ffma2(wC.x, v.x, a[8]);   a[9]  = ffma2(wC.x, v.y, a[9]);
        a[10] = ffma2(wC.y, v.x, a[10]);  a[11] = ffma2(wC.y, v.y, a[11]);
        a[12] = ffma2(wD.x, v.x, a[12]);  a[13] = ffma2(wD.x, v.y, a[13]);
        a[14] = ffma2(wD.y, v.x, a[14]);  a[15] = ffma2(wD.y, v.y, a[15]);
    }
}

// NR-row GEMM slice: 4 cols x 2 pair-ulls, ring-8 global prefetch.
template<int NR>
__device__ __forceinline__ void gemm_c4(const ulonglong2* __restrict__ vsrc,
                                        const ull* __restrict__ wp,
                                        ull* __restrict__ a) {
    ulonglong2 rg[8];
#pragma unroll
    for (int i = 0; i < 8; i++) rg[i] = vsrc[i * 16];
#pragma unroll 8
    for (int r = 0; r < NR - 8; r++) {
        ulonglong2 v = rg[r & 7];
        rg[r & 7] = vsrc[(r + 8) * 16];
        const ull* w = wp + r * 8;
        ulonglong2 wA = *reinterpret_cast<const ulonglong2*>(w);
        ulonglong2 wB = *reinterpret_cast<const ulonglong2*>(w + 2);
        a[0] = ffma2(wA.x, v.x, a[0]);  a[1] = ffma2(wA.x, v.y, a[1]);
        a[2] = ffma2(wA.y, v.x, a[2]);  a[3] = ffma2(wA.y, v.y, a[3]);
        a[4] = ffma2(wB.x, v.x, a[4]);  a[5] = ffma2(wB.x, v.y, a[5]);
        a[6] = ffma2(wB.y, v.x, a[6]);  a[7] = ffma2(wB.y, v.y, a[7]);
    }
#pragma unroll
    for (int r = NR - 8; r < NR; r++) {
        ulonglong2 v = rg[r & 7];
        const ull* w = wp + r * 8;
        ulonglong2 wA = *reinterpret_cast<const ulonglong2*>(w);
        ulonglong2 wB = *reinterpret_cast<const ulonglong2*>(w + 2);
        a[0] = ffma2(wA.x, v.x, a[0]);  a[1] = ffma2(wA.x, v.y, a[1]);
        a[2] = ffma2(wA.y, v.x, a[2]);  a[3] = ffma2(wA.y, v.y, a[3]);
        a[4] = ffma2(wB.x, v.x, a[4]);  a[5] = ffma2(wB.x, v.y, a[5]);
        a[6] = ffma2(wB.y, v.x, a[6]);  a[7] = ffma2(wB.y, v.y, a[7]);
    }
}

__global__ void __launch_bounds__(NTHR, 1)
lstm2_kernel(const float* __restrict__ x,
             const float* __restrict__ Wih0, const float* __restrict__ bih0,
             const float* __restrict__ Whh0, const float* __restrict__ bhh0,
             const float* __restrict__ Wih1, const float* __restrict__ bih1,
             const float* __restrict__ Whh1, const float* __restrict__ bhh1,
             float* __restrict__ out)
{
    extern __shared__ char smraw[];
    ull*   w0d    = reinterpret_cast<ull*>(smraw);            // [512][16] Whh0, lane-dup
    ull*   w1d    = w0d + 512 * 16;                           // [768][8]  Wih1+Whh1
    float* bcol   = reinterpret_cast<float*>(w1d + 768 * 8);  // [24] pad 32
    float* gates0 = bcol + 32;                                // [16][64]
    float* gates1 = gates0 + 16 * BATCH;                      // [8][64]
    ull*   red0   = reinterpret_cast<ull*>(gates1 + 8 * BATCH); // [16][12][32]
    ull*   red1   = red0 + 16 * 12 * 32;                      // [8][12][32]
    ull*   wih    = red0;                                     // phase-1 alias: [256][16]

    const int tid  = threadIdx.x;
    const int cta  = blockIdx.x;
    const int wrp  = tid >> 5;
    const int lane = tid & 31;
    const int pg   = lane >> 1;          // pair group 0..15 (pairs 2pg,2pg+1)
    const int cl   = lane & 1;           // col half

    // ---- one-time: transpose x (B,T,K) -> g_xT (T,K,B) ----
    {
        const size_t total = (size_t)BATCH * T_STEPS * 64;    // float4 groups
        for (size_t idx = (size_t)cta * NTHR + tid; idx < total; idx += (size_t)NCTA * NTHR) {
            int b  = (int)(idx & 63);
            size_t r = idx >> 6;
            int kg = (int)(r & 63);
            int t  = (int)(r >> 6);
            float4 v4 = *reinterpret_cast<const float4*>(
                x + ((size_t)b * T_STEPS + t) * 256 + kg * 4);
            float* dst = g_xT + ((size_t)t * 256 + kg * 4) * BATCH + b;
            dst[0 * BATCH] = v4.x;
            dst[1 * BATCH] = v4.y;
            dst[2 * BATCH] = v4.z;
            dst[3 * BATCH] = v4.w;
        }
    }

    // ---- one-time: stage weights into smem (lane-duplicated for f32x2) ----
    // w0d col c = g*4 + u -> Whh0 global col j = g*512 + cta*4 + u
    for (int idx = tid; idx < 512 * 16; idx += NTHR) {
        int k = idx >> 4, c = idx & 15;
        int g = c >> 2, u = c & 3;
        int j = g * 512 + cta * 4 + u;
        w0d[idx] = dup32(Whh0[(size_t)k * 2048 + j]);
    }
    // w1d col c = g*2 + u1 -> global j = g*256 + cta*2 + u1
    for (int idx = tid; idx < 768 * 8; idx += NTHR) {
        int k = idx >> 3, c = idx & 7;
        int g = c >> 1, u1 = c & 1;
        int j = g * 256 + cta * 2 + u1;
        float w = (k < 512) ? Wih1[(size_t)k * 1024 + j]
                            : Whh1[(size_t)(k - 512) * 1024 + j];
        w1d[idx] = dup32(w);
    }
    // wih (aliased on red0): [256][16] from Wih0, for the precompute phase
    for (int idx = tid; idx < 256 * 16; idx += NTHR) {
        int k = idx >> 4, c = idx & 15;
        int g = c >> 2, u = c & 3;
        int j = g * 512 + cta * 4 + u;
        wih[idx] = dup32(Wih0[(size_t)k * 2048 + j]);
    }
    if (tid < 16) {
        int g = tid >> 2, u = tid & 3;
        int j = g * 512 + cta * 4 + u;
        bcol[tid] = bih0[j] + bhh0[j];
    } else if (tid < 24) {
        int c = tid - 16, g = c >> 1, u1 = c & 1;
        int j = g * 256 + cta * 2 + u1;
        bcol[tid] = bih1[j] + bhh1[j];
    }

    __syncthreads();
    grid_barrier();     // g_xT complete (read by all CTAs below)

    // ---- phase 1: precompute xg0[t] = Wih0^T x_t for own 16 cols, all t ----
    for (int t = wrp; t < T_STEPS; t += 24) {
        ull a[16];
#pragma unroll
        for (int j = 0; j < 16; j++) a[j] = 0ull;
        gemm_c8<256>(reinterpret_cast<const ulonglong2*>(
                         g_xT + (size_t)t * 16384) + pg,
                     wih + cl * 8, a);
        float* dst = g_xg0 + ((size_t)cta * T_STEPS + t) * 1024 + (cl * 8) * 64 + 4 * pg;
#pragma unroll
        for (int j = 0; j < 8; j++)
            *reinterpret_cast<ulonglong2*>(dst + j * 64) =
                make_ulonglong2(a[2 * j], a[2 * j + 1]);
    }
    __syncthreads();    // wih (red0) now free for reduction use

    // balanced row assignment (computed once)
    const bool loW = (wrp < 16);
    const int  l0lo = loW ? (22 * wrp) : (352 + 20 * (wrp - 16));   // L0 h0 row base
    const int  l1lo = loW ? (32 * wrp) : (32 * (wrp - 16));         // L1 row base (h0 or h1)
    const ull* w0p  = w0d + (size_t)l0lo * 16 + cl * 8;
    const ull* w1p  = w1d + (size_t)((loW ? 0 : 512) + l1lo) * 8 + cl * 4;

    float cst = 0.0f;   // c0 for tid<256 (unit tid>>6, batch tid&63); c1 for [256,384)

    // ---- phase 2: recurrence. iteration t = layer0 step t + layer1 step t-1 ----
    for (int t = 0; t <= T_STEPS; t++) {
        const bool hasL0 = (t < T_STEPS);
        const bool hasL1 = (t >= 1);

        // early xg0 fetch (consumed ~4K cyc later in the reduce)
        ull xg = 0ull;
        if (hasL0 && tid < 512)
            xg = *reinterpret_cast<const ull*>(
                g_xg0 + ((size_t)cta * T_STEPS + t) * 1024 + (tid >> 5) * 64 + 2 * (tid & 31));

        ull a0[16], a1[8];
#pragma unroll
        for (int j = 0; j < 16; j++) a0[j] = 0ull;
#pragma unroll
        for (int j = 0; j < 8; j++) a1[j] = 0ull;

        const float* h0prev = g_h0[(t - 1) & 1];

        // ---- L0 slice (h0_{t-1}) ----
        if (hasL0 && t >= 1) {
            const ulonglong2* vp = reinterpret_cast<const ulonglong2*>(
                h0prev + l0lo * 64) + pg;
            if (loW) gemm_c8<22>(vp, w0p, a0);
            else     gemm_c8<20>(vp, w0p, a0);
        }
        // ---- L1 slice: warps 0-15 h0-part, warps 16-23 h1-part ----
        if (hasL1 && (loW || t >= 2)) {
            const float* s1 = loW ? (h0prev + l1lo * 64)
                                  : (g_h1[t & 1] + l1lo * 64);
            gemm_c4<32>(reinterpret_cast<const ulonglong2*>(s1) + pg, w1p, a1);
        }

        // ---- 2-wave reduction into 12 slots ----
        const int slot = (wrp < 12) ? wrp : (wrp - 12);
        if (wrp < 12) {
#pragma unroll
            for (int j = 0; j < 8; j++)
                *reinterpret_cast<ulonglong2*>(
                    red0 + ((cl * 8 + j) * 12 + slot) * 32 + 2 * pg) =
                    make_ulonglong2(a0[2 * j], a0[2 * j + 1]);
#pragma unroll
            for (int j = 0; j < 4; j++)
                *reinterpret_cast<ulonglong2*>(
                    red1 + ((cl * 4 + j) * 12 + slot) * 32 + 2 * pg) =
                    make_ulonglong2(a1[2 * j], a1[2 * j + 1]);
        }
        __syncthreads();
        if (wrp >= 12) {
#pragma unroll
            for (int j = 0; j < 8; j++) {
                ull* d = red0 + ((cl * 8 + j) * 12 + slot) * 32 + 2 * pg;
                ulonglong2 r = *reinterpret_cast<ulonglong2*>(d);
                r.x = addf2(r.x, a0[2 * j]); r.y = addf2(r.y, a0[2 * j + 1]);
                *reinterpret_cast<ulonglong2*>(d) = r;
            }
#pragma unroll
            for (int j = 0; j < 4; j++) {
                ull* d = red1 + ((cl * 4 + j) * 12 + slot) * 32 + 2 * pg;
                ulonglong2 r = *reinterpret_cast<ulonglong2*>(d);
                r.x = addf2(r.x, a1[2 * j]); r.y = addf2(r.y, a1[2 * j + 1]);
                *reinterpret_cast<ulonglong2*>(d) = r;
            }
        }
        __syncthreads();

        // ---- final reduce: gates = bias (+xg0) + sum of 12 slots ----
        if (tid < 512) {
            const int cc = tid >> 5, pr = tid & 31;
            const ull* r = red0 + (cc * 12) * 32 + pr;
            ull s = addf2(xg, dup32(bcol[cc]));
#pragma unroll
            for (int w = 0; w < 12; w++) s = addf2(s, r[w * 32]);
            *reinterpret_cast<ull*>(&gates0[cc * 64 + 2 * pr]) = s;
        } else {
            const int c1 = (tid - 512) >> 5, p1 = tid & 31;
            const ull* r = red1 + (c1 * 12) * 32 + p1;
            ull s = dup32(bcol[16 + c1]);
#pragma unroll
            for (int w = 0; w < 12; w++) s = addf2(s, r[w * 32]);
            *reinterpret_cast<ull*>(&gates1[c1 * 64 + 2 * p1]) = s;
        }
        __syncthreads();

        // ---- activations (disjoint warps) ----
        if (hasL0 && tid < 256) {
            int u = tid >> 6, b = tid & 63;
            float gi = gates0[(0 * 4 + u) * 64 + b];
            float gf = gates0[(1 * 4 + u) * 64 + b];
            float gg = gates0[(2 * 4 + u) * 64 + b];
            float go = gates0[(3 * 4 + u) * 64 + b];
            cst = sigmf(gf) * cst + sigmf(gi) * tanhf(gg);
            g_h0[t & 1][(cta * 4 + u) * 64 + b] = sigmf(go) * tanhf(cst);
        }
        if (hasL1 && tid >= 256 && tid < 384) {
            int u1 = (tid >> 6) & 1, b = tid & 63;
            float gi = gates1[(0 * 2 + u1) * 64 + b];
            float gf = gates1[(1 * 2 + u1) * 64 + b];
            float gg = gates1[(2 * 2 + u1) * 64 + b];
            float go = gates1[(3 * 2 + u1) * 64 + b];
            cst = sigmf(gf) * cst + sigmf(gi) * tanhf(gg);
            float h = sigmf(go) * tanhf(cst);
            int s = t - 1;
            g_h1[s & 1][(cta * 2 + u1) * 64 + b] = h;
            out[((size_t)b * T_STEPS + s) * 256 + cta * 2 + u1] = h;
        }

        if (t < T_STEPS) grid_barrier();
    }
}

// smem: w0d 65536 + w1d 49152 + bcol 128 + gates 6144 + red0 49152 + red1 24576 = 194688
#define SMEM_BYTES (65536 + 49152 + 128 + 4096 + 2048 + 49152 + 24576)

extern "C" void kernel_launch(void* const* d_in, const int* in_sizes, int n_in,
                              void* d_out, int out_size) {
    (void)in_sizes; (void)n_in; (void)out_size;
    cudaFuncSetAttribute(lstm2_kernel,
                         cudaFuncAttributeMaxDynamicSharedMemorySize, SMEM_BYTES);
    lstm2_kernel<<<NCTA, NTHR, SMEM_BYTES>>>(
        (const float*)d_in[0],
        (const float*)d_in[1], (const float*)d_in[2],
        (const float*)d_in[3], (const float*)d_in[4],
        (const float*)d_in[5], (const float*)d_in[6],
        (const float*)d_in[7], (const float*)d_in[8],
        (float*)d_out);
}

// round 14
// speedup vs baseline: 1.3073x; 1.2852x over previous
#include <cuda_runtime.h>

typedef unsigned long long ull;

#define T_STEPS 1024
#define BATCH   64
#define NCTA    128
#define NTHR    768

// R9 skeleton (best: 17.4ms) with two changes:
//  1. Tree grid barrier: 8 leaf counters (512B apart -> distinct LTS slices) x16 CTAs,
//     leaf-finisher promotes to root, root-finisher releases. Monotone targets, no
//     mid-run resets; g_done last-CTA-out resets all counters for graph replays.
//     Replaces the single-counter barrier whose 128 same-address atomics serialize
//     at ~27cyc each (~3.5K cyc/step).
//  2. 2-wave 12-slot partial reduction (was 3-wave 8-slot): one fewer sync + RMW wave.
//
// v (K=1024 rows x 64 batch) read directly from global (L2):
//   rows [0,256) = x_t; [256,768) = h0_{t-1}; [768,1024) = h1_{t-2}
// Warp ks (0..23) owns k in [32ks,32ks+32) for BOTH layers (contiguous, no dup reads).
// Lane: pg=(lane>>1) -> pairs 2pg,2pg+1; cl=lane&1 -> col half.
// Accums: a0[16] + a1[8] = 24 ull.

__device__ float g_xT[T_STEPS * 256 * BATCH];   // x transposed to [t][k][b]
__device__ float g_h0[2][512 * BATCH];
__device__ float g_h1[2][256 * BATCH];
__device__ unsigned g_leaf[8 * 128];            // leaf counters, 512B stride
__device__ unsigned g_root = 0;
__device__ unsigned g_rel  = 0;
__device__ unsigned g_done = 0;

__device__ __forceinline__ ull ffma2(ull a, ull b, ull c) {
    ull d;
    asm("fma.rn.f32x2 %0, %1, %2, %3;" : "=l"(d) : "l"(a), "l"(b), "l"(c));
    return d;
}
__device__ __forceinline__ ull addf2(ull a, ull b) {
    ull d;
    asm("add.rn.f32x2 %0, %1, %2;" : "=l"(d) : "l"(a), "l"(b));
    return d;
}
__device__ __forceinline__ ull dup32(float w) {
    unsigned u = __float_as_uint(w);
    return ((ull)u << 32) | (ull)u;
}
__device__ __forceinline__ float sigmf(float x) {
    return 1.0f / (1.0f + __expf(-x));
}

// Tree grid barrier, sequence number s (monotone per launch).
// Safe: ~222KB smem -> 1 CTA/SM, 128 CTAs <= 148 SMs, all co-resident in wave 1.
__device__ __forceinline__ void grid_barrier(int& s) {
    __syncthreads();
    if (threadIdx.x == 0) {
        s += 1;
        __threadfence();
        unsigned old = atomicAdd(&g_leaf[(blockIdx.x >> 4) * 128], 1u);
        if (old + 1u == 16u * (unsigned)s) {              // last in leaf -> promote
            unsigned old2 = atomicAdd(&g_root, 1u);
            if (old2 + 1u == 8u * (unsigned)s) {          // last leaf -> release
                __threadfence();
                atomicAdd(&g_rel, 1u);
            }
        }
        while (*(volatile unsigned*)&g_rel < (unsigned)s) __nanosleep(32);
        __threadfence();
    }
    __syncthreads();
}

// 32-row GEMM slice, 8 cols x 2 pair-ulls, depth-2 v ring (R9-proven).
__device__ __forceinline__ void gemm32_c8(const ulonglong2* __restrict__ vsrc,
                                          const ull* __restrict__ wp,
                                          ull* __restrict__ a) {
    ulonglong2 v0 = vsrc[0];
    ulonglong2 v1 = vsrc[16];
    const ulonglong2* vnext = vsrc + 32;
#pragma unroll 2
    for (int r = 0; r < 32; r++) {
        ulonglong2 v = (r & 1) ? v1 : v0;
        if (r + 2 < 32) {
            if (r & 1) v1 = *vnext; else v0 = *vnext;
            vnext += 16;
        }
        ulonglong2 wA = *reinterpret_cast<const ulonglong2*>(wp);
        ulonglong2 wB = *reinterpret_cast<const ulonglong2*>(wp + 2);
        a[0]  = ffma2(wA.x, v.x, a[0]);   a[1]  = ffma2(wA.x, v.y, a[1]);
        a[2]  = ffma2(wA.y, v.x, a[2]);   a[3]  = ffma2(wA.y, v.y, a[3]);
        a[4]  = ffma2(wB.x, v.x, a[4]);   a[5]  = ffma2(wB.x, v.y, a[5]);
        a[6]  = ffma2(wB.y, v.x, a[6]);   a[7]  = ffma2(wB.y, v.y, a[7]);
        ulonglong2 wC = *reinterpret_cast<const ulonglong2*>(wp + 4);
        ulonglong2 wD = *reinterpret_cast<const ulonglong2*>(wp + 6);
        wp += 16;
        a[8]  = ffma2(wC.x, v.x, a[8]);   a[9]  = ffma2(wC.x, v.y, a[9]);
        a[10] = ffma2(wC.y, v.x, a[10]);  a[11] = ffma2(wC.y, v.y, a[11]);
        a[12] = ffma2(wD.x, v.x, a[12]);  a[13] = ffma2(wD.x, v.y, a[13]);
        a[14] = ffma2(wD.y, v.x, a[14]);  a[15] = ffma2(wD.y, v.y, a[15]);
    }
}

// 32-row GEMM slice, 4 cols x 2 pair-ulls, depth-2 v ring.
__device__ __forceinline__ void gemm32_c4(const ulonglong2* __restrict__ vsrc,
                                          const ull* __restrict__ wp,
                                          ull* __restrict__ a) {
    ulonglong2 v0 = vsrc[0];
    ulonglong2 v1 = vsrc[16];
    const ulonglong2* vnext = vsrc + 32;
#pragma unroll 2
    for (int r = 0; r < 32; r++) {
        ulonglong2 v = (r & 1) ? v1 : v0;
        if (r + 2 < 32) {
            if (r & 1) v1 = *vnext; else v0 = *vnext;
            vnext += 16;
        }
        ulonglong2 wA = *reinterpret_cast<const ulonglong2*>(wp);
        ulonglong2 wB = *reinterpret_cast<const ulonglong2*>(wp + 2);
        wp += 8;
        a[0] = ffma2(wA.x, v.x, a[0]);  a[1] = ffma2(wA.x, v.y, a[1]);
        a[2] = ffma2(wA.y, v.x, a[2]);  a[3] = ffma2(wA.y, v.y, a[3]);
        a[4] = ffma2(wB.x, v.x, a[4]);  a[5] = ffma2(wB.x, v.y, a[5]);
        a[6] = ffma2(wB.y, v.x, a[6]);  a[7] = ffma2(wB.y, v.y, a[7]);
    }
}

__global__ void __launch_bounds__(NTHR, 1)
lstm2_kernel(const float* __restrict__ x,
             const float* __restrict__ Wih0, const float* __restrict__ bih0,
             const float* __restrict__ Whh0, const float* __restrict__ bhh0,
             const float* __restrict__ Wih1, const float* __restrict__ bih1,
             const float* __restrict__ Whh1, const float* __restrict__ bhh1,
             float* __restrict__ out)
{
    extern __shared__ char smraw[];
    ull*   w0d    = reinterpret_cast<ull*>(smraw);            // [768][16] lane-dup
    ull*   w1d    = w0d + 768 * 16;                           // [768][8]
    float* bcol   = reinterpret_cast<float*>(w1d + 768 * 8);  // [24] pad 32
    float* gates0 = bcol + 32;                                // [16][64]
    float* gates1 = gates0 + 16 * BATCH;                      // [8][64]
    ull*   red0   = reinterpret_cast<ull*>(gates1 + 8 * BATCH); // [16][12][32]
    ull*   red1   = red0 + 16 * 12 * 32;                      // [8][12][32]

    const int tid = threadIdx.x;
    const int cta = blockIdx.x;
    const int ks  = tid >> 5;            // warp id 0..23: k in [32ks, 32ks+32)
    const int pg  = (tid & 31) >> 1;     // pair group 0..15
    const int cl  = tid & 1;             // col half
    int bar_s = 0;                       // barrier sequence (thread 0 uses)

    // ---- one-time: transpose x (B,T,K) -> g_xT (T,K,B) ----
    {
        const size_t total = (size_t)BATCH * T_STEPS * 64;    // float4 groups
        for (size_t idx = (size_t)cta * NTHR + tid; idx < total; idx += (size_t)NCTA * NTHR) {
            int b  = (int)(idx & 63);
            size_t r = idx >> 6;
            int kg = (int)(r & 63);
            int t  = (int)(r >> 6);
            float4 v4 = *reinterpret_cast<const float4*>(
                x + ((size_t)b * T_STEPS + t) * 256 + kg * 4);
            float* dst = g_xT + ((size_t)t * 256 + kg * 4) * BATCH + b;
            dst[0 * BATCH] = v4.x;
            dst[1 * BATCH] = v4.y;
            dst[2 * BATCH] = v4.z;
            dst[3 * BATCH] = v4.w;
        }
    }

    // ---- one-time: stage weights into smem (lane-duplicated for f32x2) ----
    // L0 smem col cc = g*4 + u -> global j = g*512 + cta*4 + u
    for (int idx = tid; idx < 768 * 16; idx += NTHR) {
        int k = idx >> 4, cc = idx & 15;
        int g = cc >> 2, u = cc & 3;
        int j = g * 512 + cta * 4 + u;
        float w = (k < 256) ? Wih0[(size_t)k * 2048 + j]
                            : Whh0[(size_t)(k - 256) * 2048 + j];
        w0d[idx] = dup32(w);
    }
    // L1 smem col cc = g*2 + u1 -> global j = g*256 + cta*2 + u1
    for (int idx = tid; idx < 768 * 8; idx += NTHR) {
        int k = idx >> 3, cc = idx & 7;
        int g = cc >> 1, u1 = cc & 1;
        int j = g * 256 + cta * 2 + u1;
        float w = (k < 512) ? Wih1[(size_t)k * 1024 + j]
                            : Whh1[(size_t)(k - 512) * 1024 + j];
        w1d[idx] = dup32(w);
    }
    if (tid < 16) {
        int g = tid >> 2, u = tid & 3;
        int j = g * 512 + cta * 4 + u;
        bcol[tid] = bih0[j] + bhh0[j];
    } else if (tid < 24) {
        int cc = tid - 16, g = cc >> 1, u1 = cc & 1;
        int j = g * 256 + cta * 2 + u1;
        bcol[tid] = bih1[j] + bhh1[j];
    }

    float cst = 0.0f;   // c0 for tid<256 (unit tid>>6, batch tid&63); c1 for [256,384)

    grid_barrier(bar_s);     // g_xT complete

    // ---- main recurrence: iteration t = layer0 step t + layer1 step t-1 ----
    for (int t = 0; t <= T_STEPS; t++) {
        const bool hasL0 = (t < T_STEPS);
        const bool hasL1 = (t >= 1);

        ull a0[16], a1[8];
#pragma unroll
        for (int j = 0; j < 16; j++) a0[j] = 0ull;
#pragma unroll
        for (int j = 0; j < 8; j++) a1[j] = 0ull;

        // ---- L0 slice: k in [32ks, 32ks+32); sources: ks<8 -> x_t, else h0_{t-1} ----
        if (hasL0 && (ks < 8 || t >= 1)) {
            const float* src = (ks < 8)
                ? (g_xT + (size_t)t * 16384 + ks * 2048)
                : (g_h0[(t - 1) & 1] + (ks - 8) * 2048);
            gemm32_c8(reinterpret_cast<const ulonglong2*>(src) + pg,
                      w0d + (size_t)(32 * ks) * 16 + cl * 8, a0);
        }
        // ---- L1 slice: local k1 in [32ks, 32ks+32); ks<16 -> h0_{t-1}, else h1_{t-2} ----
        if (hasL1 && (ks < 16 || t >= 2)) {
            const float* src = (ks < 16)
                ? (g_h0[(t - 1) & 1] + ks * 2048)
                : (g_h1[t & 1] + (ks - 16) * 2048);
            gemm32_c4(reinterpret_cast<const ulonglong2*>(src) + pg,
                      w1d + (size_t)(32 * ks) * 8 + cl * 4, a1);
        }

        // ---- 2-wave ks reduction into 12 slots ----
        const int slot = (ks < 12) ? ks : (ks - 12);
        if (ks < 12) {
#pragma unroll
            for (int j = 0; j < 8; j++)
                *reinterpret_cast<ulonglong2*>(
                    red0 + ((cl * 8 + j) * 12 + slot) * 32 + 2 * pg) =
                    make_ulonglong2(a0[2 * j], a0[2 * j + 1]);
#pragma unroll
            for (int j = 0; j < 4; j++)
                *reinterpret_cast<ulonglong2*>(
                    red1 + ((cl * 4 + j) * 12 + slot) * 32 + 2 * pg) =
                    make_ulonglong2(a1[2 * j], a1[2 * j + 1]);
        }
        __syncthreads();
        if (ks >= 12) {
#pragma unroll
            for (int j = 0; j < 8; j++) {
                ull* d = red0 + ((cl * 8 + j) * 12 + slot) * 32 + 2 * pg;
                ulonglong2 r = *reinterpret_cast<ulonglong2*>(d);
                r.x = addf2(r.x, a0[2 * j]); r.y = addf2(r.y, a0[2 * j + 1]);
                *reinterpret_cast<ulonglong2*>(d) = r;
            }
#pragma unroll
            for (int j = 0; j < 4; j++) {
                ull* d = red1 + ((cl * 4 + j) * 12 + slot) * 32 + 2 * pg;
                ulonglong2 r = *reinterpret_cast<ulonglong2*>(d);
                r.x = addf2(r.x, a1[2 * j]); r.y = addf2(r.y, a1[2 * j + 1]);
                *reinterpret_cast<ulonglong2*>(d) = r;
            }
        }
        __syncthreads();

        // ---- final: sum 12 slots + bias -> gates (one ull per thread) ----
        if (tid < 512) {
            int cc = tid >> 5, pr = tid & 31;
            const ull* r = red0 + (cc * 12) * 32 + pr;
            ull s = dup32(bcol[cc]);
#pragma unroll
            for (int w = 0; w < 12; w++) s = addf2(s, r[w * 32]);
            *reinterpret_cast<ull*>(&gates0[cc * 64 + 2 * pr]) = s;
        } else {
            int i = tid - 512, cc = i >> 5, pr = i & 31;
            const ull* r = red1 + (cc * 12) * 32 + pr;
            ull s = dup32(bcol[16 + cc]);
#pragma unroll
            for (int w = 0; w < 12; w++) s = addf2(s, r[w * 32]);
            *reinterpret_cast<ull*>(&gates1[cc * 64 + 2 * pr]) = s;
        }
        __syncthreads();

        // ---- activations (disjoint warps) ----
        if (hasL0 && tid < 256) {
            int u = tid >> 6, b = tid & 63;
            float gi = gates0[(0 * 4 + u) * 64 + b];
            float gf = gates0[(1 * 4 + u) * 64 + b];
            float gg = gates0[(2 * 4 + u) * 64 + b];
            float go = gates0[(3 * 4 + u) * 64 + b];
            cst = sigmf(gf) * cst + sigmf(gi) * tanhf(gg);
            g_h0[t & 1][(cta * 4 + u) * 64 + b] = sigmf(go) * tanhf(cst);
        }
        if (hasL1 && tid >= 256 && tid < 384) {
            int u1 = (tid >> 6) & 1, b = tid & 63;
            float gi = gates1[(0 * 2 + u1) * 64 + b];
            float gf = gates1[(1 * 2 + u1) * 64 + b];
            float gg = gates1[(2 * 2 + u1) * 64 + b];
            float go = gates1[(3 * 2 + u1) * 64 + b];
            cst = sigmf(gf) * cst + sigmf(gi) * tanhf(gg);
            float h = sigmf(go) * tanhf(cst);
            int s = t - 1;
            g_h1[s & 1][(cta * 2 + u1) * 64 + b] = h;
            out[((size_t)b * T_STEPS + s) * 256 + cta * 2 + u1] = h;
        }

        if (t < T_STEPS) grid_barrier(bar_s);
    }

    // ---- last CTA out resets all barrier counters (graph-replay safe) ----
    if (threadIdx.x == 0) {
        __threadfence();
        unsigned old = atomicAdd(&g_done, 1u);
        if (old == (unsigned)(NCTA - 1)) {
#pragma unroll
            for (int i = 0; i < 8; i++) g_leaf[i * 128] = 0u;
            g_root = 0u;
            g_rel  = 0u;
            __threadfence();
            g_done = 0u;
        }
    }
}

// smem: w0d 98304 + w1d 49152 + bcol 128 + gates 6144 + red0 49152 + red1 24576 = 227456
#define SMEM_BYTES (98304 + 49152 + 128 + 4096 + 2048 + 49152 + 24576)

extern "C" void kernel_launch(void* const* d_in, const int* in_sizes, int n_in,
                              void* d_out, int out_size) {
    (void)in_sizes; (void)n_in; (void)out_size;
    cudaFuncSetAttribute(lstm2_kernel,
                         cudaFuncAttributeMaxDynamicSharedMemorySize, SMEM_BYTES);
    lstm2_kernel<<<NCTA, NTHR, SMEM_BYTES>>>(
        (const float*)d_in[0],
        (const float*)d_in[1], (const float*)d_in[2],
        (const float*)d_in[3], (const float*)d_in[4],
        (const float*)d_in[5], (const float*)d_in[6],
        (const float*)d_in[7], (const float*)d_in[8],
        (float*)d_out);
}

// round 15
// speedup vs baseline: 1.4823x; 1.1338x over previous
#include <cuda_runtime.h>

typedef unsigned long long ull;

#define T_STEPS 1024
#define BATCH   64
#define NCTA    128
#define NTHR    768

// R14 skeleton (best: 16.1ms — tree barrier + 2-wave 12-slot reduction) with ONE change:
//   GEMM inner loops FULLY UNROLLED with immediate-offset addressing (no pointer
//   mutation, no ring muxing) -> ptxas emits LDS.128/LDG.128 [R+imm] and schedules
//   load depth itself. Targets the 13.3% alu / ~4K issue slots of loop bookkeeping.
//
// v (K=1024 rows x 64 batch) read directly from global (L2):
//   rows [0,256) = x_t; [256,768) = h0_{t-1}; [768,1024) = h1_{t-2}
// Warp ks (0..23) owns k in [32ks,32ks+32) for BOTH layers (contiguous, no dup reads).
// Lane: pg=(lane>>1) -> pairs 2pg,2pg+1; cl=lane&1 -> col half.
// Accums: a0[16] + a1[8] = 24 ull.

__device__ float g_xT[T_STEPS * 256 * BATCH];   // x transposed to [t][k][b]
__device__ float g_h0[2][512 * BATCH];
__device__ float g_h1[2][256 * BATCH];
__device__ unsigned g_leaf[8 * 128];            // leaf counters, 512B stride
__device__ unsigned g_root = 0;
__device__ unsigned g_rel  = 0;
__device__ unsigned g_done = 0;

__device__ __forceinline__ ull ffma2(ull a, ull b, ull c) {
    ull d;
    asm("fma.rn.f32x2 %0, %1, %2, %3;" : "=l"(d) : "l"(a), "l"(b), "l"(c));
    return d;
}
__device__ __forceinline__ ull addf2(ull a, ull b) {
    ull d;
    asm("add.rn.f32x2 %0, %1, %2;" : "=l"(d) : "l"(a), "l"(b));
    return d;
}
__device__ __forceinline__ ull dup32(float w) {
    unsigned u = __float_as_uint(w);
    return ((ull)u << 32) | (ull)u;
}
__device__ __forceinline__ float sigmf(float x) {
    return 1.0f / (1.0f + __expf(-x));
}

// Tree grid barrier, sequence number s (monotone per launch).
// Safe: ~222KB smem -> 1 CTA/SM, 128 CTAs <= 148 SMs, all co-resident in wave 1.
__device__ __forceinline__ void grid_barrier(int& s) {
    __syncthreads();
    if (threadIdx.x == 0) {
        s += 1;
        __threadfence();
        unsigned old = atomicAdd(&g_leaf[(blockIdx.x >> 4) * 128], 1u);
        if (old + 1u == 16u * (unsigned)s) {              // last in leaf -> promote
            unsigned old2 = atomicAdd(&g_root, 1u);
            if (old2 + 1u == 8u * (unsigned)s) {          // last leaf -> release
                __threadfence();
                atomicAdd(&g_rel, 1u);
            }
        }
        while (*(volatile unsigned*)&g_rel < (unsigned)s) __nanosleep(32);
        __threadfence();
    }
    __syncthreads();
}

// 32-row GEMM slice, 8 cols x 2 pair-ulls. FULLY UNROLLED, immediate offsets.
// vsrc: ulonglong2 base (already + pg), row stride 16 ulonglong2 (256B).
__device__ __forceinline__ void gemm32_c8(const ulonglong2* __restrict__ vsrc,
                                          const ull* __restrict__ wp,
                                          ull* __restrict__ a) {
#pragma unroll
    for (int r = 0; r < 32; r++) {
        ulonglong2 v  = vsrc[r * 16];
        ulonglong2 wA = *reinterpret_cast<const ulonglong2*>(wp + r * 16);
        ulonglong2 wB = *reinterpret_cast<const ulonglong2*>(wp + r * 16 + 2);
        ulonglong2 wC = *reinterpret_cast<const ulonglong2*>(wp + r * 16 + 4);
        ulonglong2 wD = *reinterpret_cast<const ulonglong2*>(wp + r * 16 + 6);
        a[0]  = ffma2(wA.x, v.x, a[0]);   a[1]  = ffma2(wA.x, v.y, a[1]);
        a[2]  = ffma2(wA.y, v.x, a[2]);   a[3]  = ffma2(wA.y, v.y, a[3]);
        a[4]  = ffma2(wB.x, v.x, a[4]);   a[5]  = ffma2(wB.x, v.y, a[5]);
        a[6]  = ffma2(wB.y, v.x, a[6]);   a[7]  = ffma2(wB.y, v.y, a[7]);
        a[8]  = ffma2(wC.x, v.x, a[8]);   a[9]  = ffma2(wC.x, v.y, a[9]);
        a[10] = ffma2(wC.y, v.x, a[10]);  a[11] = ffma2(wC.y, v.y, a[11]);
        a[12] = ffma2(wD.x, v.x, a[12]);  a[13] = ffma2(wD.x, v.y, a[13]);
        a[14] = ffma2(wD.y, v.x, a[14]);  a[15] = ffma2(wD.y, v.y, a[15]);
    }
}

// 32-row GEMM slice, 4 cols x 2 pair-ulls. FULLY UNROLLED, immediate offsets.
__device__ __forceinline__ void gemm32_c4(const ulonglong2* __restrict__ vsrc,
                                          const ull* __restrict__ wp,
                                          ull* __restrict__ a) {
#pragma unroll
    for (int r = 0; r < 32; r++) {
        ulonglong2 v  = vsrc[r * 16];
        ulonglong2 wA = *reinterpret_cast<const ulonglong2*>(wp + r * 8);
        ulonglong2 wB = *reinterpret_cast<const ulonglong2*>(wp + r * 8 + 2);
        a[0] = ffma2(wA.x, v.x, a[0]);  a[1] = ffma2(wA.x, v.y, a[1]);
        a[2] = ffma2(wA.y, v.x, a[2]);  a[3] = ffma2(wA.y, v.y, a[3]);
        a[4] = ffma2(wB.x, v.x, a[4]);  a[5] = ffma2(wB.x, v.y, a[5]);
        a[6] = ffma2(wB.y, v.x, a[6]);  a[7] = ffma2(wB.y, v.y, a[7]);
    }
}

__global__ void __launch_bounds__(NTHR, 1)
lstm2_kernel(const float* __restrict__ x,
             const float* __restrict__ Wih0, const float* __restrict__ bih0,
             const float* __restrict__ Whh0, const float* __restrict__ bhh0,
             const float* __restrict__ Wih1, const float* __restrict__ bih1,
             const float* __restrict__ Whh1, const float* __restrict__ bhh1,
             float* __restrict__ out)
{
    extern __shared__ char smraw[];
    ull*   w0d    = reinterpret_cast<ull*>(smraw);            // [768][16] lane-dup
    ull*   w1d    = w0d + 768 * 16;                           // [768][8]
    float* bcol   = reinterpret_cast<float*>(w1d + 768 * 8);  // [24] pad 32
    float* gates0 = bcol + 32;                                // [16][64]
    float* gates1 = gates0 + 16 * BATCH;                      // [8][64]
    ull*   red0   = reinterpret_cast<ull*>(gates1 + 8 * BATCH); // [16][12][32]
    ull*   red1   = red0 + 16 * 12 * 32;                      // [8][12][32]

    const int tid = threadIdx.x;
    const int cta = blockIdx.x;
    const int ks  = tid >> 5;            // warp id 0..23: k in [32ks, 32ks+32)
    const int pg  = (tid & 31) >> 1;     // pair group 0..15
    const int cl  = tid & 1;             // col half
    int bar_s = 0;                       // barrier sequence (thread 0 uses)

    // ---- one-time: transpose x (B,T,K) -> g_xT (T,K,B) ----
    {
        const size_t total = (size_t)BATCH * T_STEPS * 64;    // float4 groups
        for (size_t idx = (size_t)cta * NTHR + tid; idx < total; idx += (size_t)NCTA * NTHR) {
            int b  = (int)(idx & 63);
            size_t r = idx >> 6;
            int kg = (int)(r & 63);
            int t  = (int)(r >> 6);
            float4 v4 = *reinterpret_cast<const float4*>(
                x + ((size_t)b * T_STEPS + t) * 256 + kg * 4);
            float* dst = g_xT + ((size_t)t * 256 + kg * 4) * BATCH + b;
            dst[0 * BATCH] = v4.x;
            dst[1 * BATCH] = v4.y;
            dst[2 * BATCH] = v4.z;
            dst[3 * BATCH] = v4.w;
        }
    }

    // ---- one-time: stage weights into smem (lane-duplicated for f32x2) ----
    // L0 smem col cc = g*4 + u -> global j = g*512 + cta*4 + u
    for (int idx = tid; idx < 768 * 16; idx += NTHR) {
        int k = idx >> 4, cc = idx & 15;
        int g = cc >> 2, u = cc & 3;
        int j = g * 512 + cta * 4 + u;
        float w = (k < 256) ? Wih0[(size_t)k * 2048 + j]
                            : Whh0[(size_t)(k - 256) * 2048 + j];
        w0d[idx] = dup32(w);
    }
    // L1 smem col cc = g*2 + u1 -> global j = g*256 + cta*2 + u1
    for (int idx = tid; idx < 768 * 8; idx += NTHR) {
        int k = idx >> 3, cc = idx & 7;
        int g = cc >> 1, u1 = cc & 1;
        int j = g * 256 + cta * 2 + u1;
        float w = (k < 512) ? Wih1[(size_t)k * 1024 + j]
                            : Whh1[(size_t)(k - 512) * 1024 + j];
        w1d[idx] = dup32(w);
    }
    if (tid < 16) {
        int g = tid >> 2, u = tid & 3;
        int j = g * 512 + cta * 4 + u;
        bcol[tid] = bih0[j] + bhh0[j];
    } else if (tid < 24) {
        int cc = tid - 16, g = cc >> 1, u1 = cc & 1;
        int j = g * 256 + cta * 2 + u1;
        bcol[tid] = bih1[j] + bhh1[j];
    }

    float cst = 0.0f;   // c0 for tid<256 (unit tid>>6, batch tid&63); c1 for [256,384)

    grid_barrier(bar_s);     // g_xT complete

    // ---- main recurrence: iteration t = layer0 step t + layer1 step t-1 ----
    for (int t = 0; t <= T_STEPS; t++) {
        const bool hasL0 = (t < T_STEPS);
        const bool hasL1 = (t >= 1);

        ull a0[16], a1[8];
#pragma unroll
        for (int j = 0; j < 16; j++) a0[j] = 0ull;
#pragma unroll
        for (int j = 0; j < 8; j++) a1[j] = 0ull;

        // ---- L0 slice: k in [32ks, 32ks+32); sources: ks<8 -> x_t, else h0_{t-1} ----
        if (hasL0 && (ks < 8 || t >= 1)) {
            const float* src = (ks < 8)
                ? (g_xT + (size_t)t * 16384 + ks * 2048)
                : (g_h0[(t - 1) & 1] + (ks - 8) * 2048);
            gemm32_c8(reinterpret_cast<const ulonglong2*>(src) + pg,
                      w0d + (size_t)(32 * ks) * 16 + cl * 8, a0);
        }
        // ---- L1 slice: local k1 in [32ks, 32ks+32); ks<16 -> h0_{t-1}, else h1_{t-2} ----
        if (hasL1 && (ks < 16 || t >= 2)) {
            const float* src = (ks < 16)
                ? (g_h0[(t - 1) & 1] + ks * 2048)
                : (g_h1[t & 1] + (ks - 16) * 2048);
            gemm32_c4(reinterpret_cast<const ulonglong2*>(src) + pg,
                      w1d + (size_t)(32 * ks) * 8 + cl * 4, a1);
        }

        // ---- 2-wave ks reduction into 12 slots ----
        const int slot = (ks < 12) ? ks : (ks - 12);
        if (ks < 12) {
#pragma unroll
            for (int j = 0; j < 8; j++)
                *reinterpret_cast<ulonglong2*>(
                    red0 + ((cl * 8 + j) * 12 + slot) * 32 + 2 * pg) =
                    make_ulonglong2(a0[2 * j], a0[2 * j + 1]);
#pragma unroll
            for (int j = 0; j < 4; j++)
                *reinterpret_cast<ulonglong2*>(
                    red1 + ((cl * 4 + j) * 12 + slot) * 32 + 2 * pg) =
                    make_ulonglong2(a1[2 * j], a1[2 * j + 1]);
        }
        __syncthreads();
        if (ks >= 12) {
#pragma unroll
            for (int j = 0; j < 8; j++) {
                ull* d = red0 + ((cl * 8 + j) * 12 + slot) * 32 + 2 * pg;
                ulonglong2 r = *reinterpret_cast<ulonglong2*>(d);
                r.x = addf2(r.x, a0[2 * j]); r.y = addf2(r.y, a0[2 * j + 1]);
                *reinterpret_cast<ulonglong2*>(d) = r;
            }
#pragma unroll
            for (int j = 0; j < 4; j++) {
                ull* d = red1 + ((cl * 4 + j) * 12 + slot) * 32 + 2 * pg;
                ulonglong2 r = *reinterpret_cast<ulonglong2*>(d);
                r.x = addf2(r.x, a1[2 * j]); r.y = addf2(r.y, a1[2 * j + 1]);
                *reinterpret_cast<ulonglong2*>(d) = r;
            }
        }
        __syncthreads();

        // ---- final: sum 12 slots + bias -> gates (one ull per thread) ----
        if (tid < 512) {
            int cc = tid >> 5, pr = tid & 31;
            const ull* r = red0 + (cc * 12) * 32 + pr;
            ull s = dup32(bcol[cc]);
#pragma unroll
            for (int w = 0; w < 12; w++) s = addf2(s, r[w * 32]);
            *reinterpret_cast<ull*>(&gates0[cc * 64 + 2 * pr]) = s;
        } else {
            int i = tid - 512, cc = i >> 5, pr = i & 31;
            const ull* r = red1 + (cc * 12) * 32 + pr;
            ull s = dup32(bcol[16 + cc]);
#pragma unroll
            for (int w = 0; w < 12; w++) s = addf2(s, r[w * 32]);
            *reinterpret_cast<ull*>(&gates1[cc * 64 + 2 * pr]) = s;
        }
        __syncthreads();

        // ---- activations (disjoint warps) ----
        if (hasL0 && tid < 256) {
            int u = tid >> 6, b = tid & 63;
            float gi = gates0[(0 * 4 + u) * 64 + b];
            float gf = gates0[(1 * 4 + u) * 64 + b];
            float gg = gates0[(2 * 4 + u) * 64 + b];
            float go = gates0[(3 * 4 + u) * 64 + b];
            cst = sigmf(gf) * cst + sigmf(gi) * tanhf(gg);
            g_h0[t & 1][(cta * 4 + u) * 64 + b] = sigmf(go) * tanhf(cst);
        }
        if (hasL1 && tid >= 256 && tid < 384) {
            int u1 = (tid >> 6) & 1, b = tid & 63;
            float gi = gates1[(0 * 2 + u1) * 64 + b];
            float gf = gates1[(1 * 2 + u1) * 64 + b];
            float gg = gates1[(2 * 2 + u1) * 64 + b];
            float go = gates1[(3 * 2 + u1) * 64 + b];
            cst = sigmf(gf) * cst + sigmf(gi) * tanhf(gg);
            float h = sigmf(go) * tanhf(cst);
            int s = t - 1;
            g_h1[s & 1][(cta * 2 + u1) * 64 + b] = h;
            out[((size_t)b * T_STEPS + s) * 256 + cta * 2 + u1] = h;
        }

        if (t < T_STEPS) grid_barrier(bar_s);
    }

    // ---- last CTA out resets all barrier counters (graph-replay safe) ----
    if (threadIdx.x == 0) {
        __threadfence();
        unsigned old = atomicAdd(&g_done, 1u);
        if (old == (unsigned)(NCTA - 1)) {
#pragma unroll
            for (int i = 0; i < 8; i++) g_leaf[i * 128] = 0u;
            g_root = 0u;
            g_rel  = 0u;
            __threadfence();
            g_done = 0u;
        }
    }
}

// smem: w0d 98304 + w1d 49152 + bcol 128 + gates 6144 + red0 49152 + red1 24576 = 227456
#define SMEM_BYTES (98304 + 49152 + 128 + 4096 + 2048 + 49152 + 24576)

extern "C" void kernel_launch(void* const* d_in, const int* in_sizes, int n_in,
                              void* d_out, int out_size) {
    (void)in_sizes; (void)n_in; (void)out_size;
    cudaFuncSetAttribute(lstm2_kernel,
                         cudaFuncAttributeMaxDynamicSharedMemorySize, SMEM_BYTES);
    lstm2_kernel<<<NCTA, NTHR, SMEM_BYTES>>>(
        (const float*)d_in[0],
        (const float*)d_in[1], (const float*)d_in[2],
        (const float*)d_in[3], (const float*)d_in[4],
        (const float*)d_in[5], (const float*)d_in[6],
        (const float*)d_in[7], (const float*)d_in[8],
        (float*)d_out);
}